// round 11
// baseline (speedup 1.0000x reference)
#include <cuda_runtime.h>
#include <cuda_bf16.h>

#define BB 2
#define DD 10
#define HH 512
#define WW 512
#define HW (HH * WW)

__device__ __forceinline__ float4 fmax4(float4 a, float4 b) {
    return make_float4(fmaxf(a.x, b.x), fmaxf(a.y, b.y), fmaxf(a.z, b.z), fmaxf(a.w, b.w));
}

__global__ __launch_bounds__(256, 4)   // 64 regs, 4 CTAs/SM
void quadinterp3d_kernel(const float* __restrict__ x, float* __restrict__ out) {
    // Block = 2 complete W-rows (tid 0-127: h0, tid 128-255: h0+1); same (b,d) per block.
    // tile: 3 planes (zm,d,zp) x 4 rows (hm,h0,h1,hp) x 512 w  — the block's full stencil input.
    __shared__ float tile[3 * 4 * WW];            // 24 KB
    __shared__ float sCmX[256], sCmW[256], sV4X[256], sV4W[256];
    __shared__ unsigned short q[512];             // (tid<<2 | j) codes of detected maxima
    __shared__ int qcnt;

    const int tid  = threadIdx.x;
    const int gid  = blockIdx.x * 256 + tid;
    const int lane = tid & 31;
    const int w4 = gid & 127;
    const int h  = (gid >> 7) & 511;
    const int t  = gid >> 16;            // 0..19 (B*D)
    const int d  = t % DD;
    const int b  = t / DD;
    const int w0 = w4 << 2;

    if (tid == 0) qcnt = 0;

    const int off4 = (d * HH + h) * WW;
    const float* __restrict__ base = x + (size_t)b * DD * HW;
    const float* __restrict__ pc = base + off4 + w0;

    // Clamped row deltas (replicate padding); dzm/dzp uniform per block
    const int dym = (h > 0)      ? WW : 0;
    const int dyp = (h < HH - 1) ? WW : 0;
    const int dzm = (d > 0)      ? HW : 0;
    const int dzp = (d < DD - 1) ? HW : 0;

    // Batched independent loads: one aligned float4 per stencil row (MLP=9)
    float4 v[9];
    v[0] = *reinterpret_cast<const float4*>(pc - dzm - dym);
    v[1] = *reinterpret_cast<const float4*>(pc - dzm);
    v[2] = *reinterpret_cast<const float4*>(pc - dzm + dyp);
    v[3] = *reinterpret_cast<const float4*>(pc - dym);
    v[4] = *reinterpret_cast<const float4*>(pc);
    v[5] = *reinterpret_cast<const float4*>(pc + dyp);
    v[6] = *reinterpret_cast<const float4*>(pc + dzp - dym);
    v[7] = *reinterpret_cast<const float4*>(pc + dzp);
    v[8] = *reinterpret_cast<const float4*>(pc + dzp + dyp);

    // ---- Stage the block tile in shared memory (no duplication, conflict-free STS.128).
    //      h0-threads own local rows 0 (hm) and 1 (h0); h1-threads own rows 2 (h1) and 3 (hp).
    //      Clamped content (rows/planes at volume edges) is inherited from the clamped loads.
    {
        float4* tp = reinterpret_cast<float4*>(tile);
        if (tid < 128) {
            tp[(0 * 4 + 0) * 128 + w4] = v[0];
            tp[(1 * 4 + 0) * 128 + w4] = v[3];
            tp[(2 * 4 + 0) * 128 + w4] = v[6];
            tp[(0 * 4 + 1) * 128 + w4] = v[1];
            tp[(1 * 4 + 1) * 128 + w4] = v[4];
            tp[(2 * 4 + 1) * 128 + w4] = v[7];
        } else {
            tp[(0 * 4 + 2) * 128 + w4] = v[1];
            tp[(1 * 4 + 2) * 128 + w4] = v[4];
            tp[(2 * 4 + 2) * 128 + w4] = v[7];
            tp[(0 * 4 + 3) * 128 + w4] = v[2];
            tp[(1 * 4 + 3) * 128 + w4] = v[5];
            tp[(2 * 4 + 3) * 128 + w4] = v[8];
        }
    }

    // Column max of the 8 non-center rows
    float4 cm = fmax4(fmax4(v[0], v[1]), fmax4(v[2], v[3]));
    cm = fmax4(cm, fmax4(fmax4(v[5], v[6]), fmax4(v[7], v[8])));

    // Block-level edge exchange
    sCmX[tid] = cm.x;  sCmW[tid] = cm.w;
    sV4X[tid] = v[4].x; sV4W[tid] = v[4].w;
    __syncthreads();   // orders tile + exchange stores before all reads below

    const bool atL = (w4 == 0);
    const bool atR = (w4 == 127);
    const float cmL = atL ? cm.x   : sCmW[tid - 1];
    const float cmR = atR ? cm.w   : sCmX[tid + 1];
    const float u0  = atL ? v[4].x : sV4W[tid - 1];
    const float u5  = atR ? v[4].w : sV4X[tid + 1];

    // Windowed max over [cmL, cm.x, cm.y, cm.z, cm.w, cmR]
    const float win0 = fmaxf(fmaxf(cmL,  cm.x), cm.y);
    const float win1 = fmaxf(fmaxf(cm.x, cm.y), cm.z);
    const float win2 = fmaxf(fmaxf(cm.y, cm.z), cm.w);
    const float win3 = fmaxf(fmaxf(cm.z, cm.w), cmR);

    // Strict-local-max mask (center row excludes the center element)
    const float nm0 = fmaxf(fmaxf(win0, fmaxf(u0,     v[4].y)), 0.0f);
    const float nm1 = fmaxf(fmaxf(win1, fmaxf(v[4].x, v[4].z)), 0.0f);
    const float nm2 = fmaxf(fmaxf(win2, fmaxf(v[4].y, v[4].w)), 0.0f);
    const float nm3 = fmaxf(fmaxf(win3, fmaxf(v[4].z, u5)),     0.0f);

    const bool m0 = v[4].x > nm0;
    const bool m1 = v[4].y > nm1;
    const bool m2 = v[4].z > nm2;
    const bool m3 = v[4].w > nm3;

    // ---- Default stores (coords = grid, y = x). Queue phase (after the next
    //      __syncthreads) overwrites the maxima entries. ----
    const size_t plsz = (size_t)DD * HW;
    const size_t inner = (size_t)off4 + w0;
    const float fd = (float)d, fh = (float)h, fw = (float)w0;
    *reinterpret_cast<float4*>(out + (size_t)(b * 3 + 0) * plsz + inner) =
        make_float4(fd, fd, fd, fd);
    *reinterpret_cast<float4*>(out + (size_t)(b * 3 + 1) * plsz + inner) =
        make_float4(fh, fh, fh, fh);
    *reinterpret_cast<float4*>(out + (size_t)(b * 3 + 2) * plsz + inner) =
        make_float4(fw, fw + 1.0f, fw + 2.0f, fw + 3.0f);
    *reinterpret_cast<float4*>(out + (size_t)BB * 3 * plsz + (size_t)b * plsz + inner) = v[4];

    // ---- Warp-aggregated queue push: one shared atomic per warp ----
    const unsigned bal0 = __ballot_sync(0xffffffffu, m0);
    const unsigned bal1 = __ballot_sync(0xffffffffu, m1);
    const unsigned bal2 = __ballot_sync(0xffffffffu, m2);
    const unsigned bal3 = __ballot_sync(0xffffffffu, m3);
    const int nWarp = __popc(bal0) + __popc(bal1) + __popc(bal2) + __popc(bal3);
    int basei = 0;
    if (lane == 0 && nWarp) basei = atomicAdd(&qcnt, nWarp);
    basei = __shfl_sync(0xffffffffu, basei, 0);
    {
        const unsigned lm = (1u << lane) - 1u;
        int p = 0;
        if (m0) q[basei + __popc(bal0 & lm)] = (unsigned short)((tid << 2) | 0);
        p += __popc(bal0);
        if (m1) q[basei + p + __popc(bal1 & lm)] = (unsigned short)((tid << 2) | 1);
        p += __popc(bal1);
        if (m2) q[basei + p + __popc(bal2 & lm)] = (unsigned short)((tid << 2) | 2);
        p += __popc(bal2);
        if (m3) q[basei + p + __popc(bal3 & lm)] = (unsigned short)((tid << 2) | 3);
    }
    __syncthreads();

    // ---- Dense queue processing: each maximum handled by one thread.
    //      All 19 stencil inputs gathered from the SMEM tile (no L1 wavefront blowup). ----
    const int cnt = qcnt;
    for (int i = tid; i < cnt; i += 256) {
        const int code = q[i];
        const int jj   = code & 3;
        const int otid = code >> 2;
        const int wq   = (((otid & 127) << 2) | jj);
        const int hq   = (blockIdx.x * 2 + (otid >> 7)) & 511;

        const int r1 = 1 + (otid >> 7);              // local tile row of hq (1 or 2)
        const int r0 = r1 + ((hq > 0)      ? -1 : 0);
        const int r2 = r1 + ((hq < HH - 1) ?  1 : 0);
        const int wl = wq + ((wq > 0)      ? -1 : 0);
        const int wr = wq + ((wq < WW - 1) ?  1 : 0);

        // tile row base indices (plane 0=zm, 1=d, 2=zp)
        #define TROW(p, r) (tile + ((p) * 4 + (r)) * WW)
        const float* q10 = TROW(1, r0);
        const float* q11 = TROW(1, r1);
        const float* q12 = TROW(1, r2);
        const float* q01 = TROW(0, r1);
        const float* q21 = TROW(2, r1);

        const float cc = q11[wq], a4 = q11[wl], c4 = q11[wr];
        const float b3 = q10[wq], a3 = q10[wl], c3 = q10[wr];
        const float b5 = q12[wq], a5 = q12[wl], c5 = q12[wr];
        const float b1 = q01[wq], a1 = q01[wl], c1 = q01[wr];
        const float b7 = q21[wq], a7 = q21[wl], c7 = q21[wr];
        const float e0 = TROW(0, r0)[wq];
        const float e2 = TROW(0, r2)[wq];
        const float e6 = TROW(2, r0)[wq];
        const float e8 = TROW(2, r2)[wq];
        #undef TROW

        // Newton solve (same algebra as the verified kernels; H symmetric)
        const float gx = 0.5f * (c4 - a4);
        const float gy = 0.5f * (b5 - b3);
        const float gs = 0.5f * (b7 - b1);

        const float h00 = a4 + c4 - 2.0f * cc;
        const float h11 = b3 + b5 - 2.0f * cc;
        const float h22 = b1 + b7 - 2.0f * cc;
        const float h01 = 0.25f * (a3 + c5 - a5 - c3);
        const float h12 = 0.25f * (e0 + e8 - e6 - e2);
        const float h02 = 0.25f * (a1 + c7 - a7 - c1);

        const float c00 = h11 * h22 - h12 * h12;
        const float c01 = h01 * h22 - h12 * h02;
        const float c02 = h01 * h12 - h11 * h02;
        const float det = h00 * c00 - h01 * c01 + h02 * c02;

        const float t1 = gy * h22 - h12 * gs;
        const float t2 = gy * h12 - h11 * gs;
        const float t3 = h01 * gs - gy * h02;

        const float inv = 1.0f / det;
        const float sx = (gx * c00 - h01 * t1 + h02 * t2) * inv;
        const float sy = (h00 * t1 - gx * c01 + h02 * t3) * inv;
        const float ss = (h00 * (h11 * gs - h12 * gy) - h01 * t3 + gx * c02) * inv;

        float d0 = -sx, d1 = -sy, d2 = -ss;
        const float far = fmaxf(fmaxf(fabsf(d0), fabsf(d1)), fabsf(d2));
        if (far > 0.7f) { d0 = 0.0f; d1 = 0.0f; d2 = 0.0f; }

        const float ry = cc + 0.5f * (gx * d0 + gy * d1 + gs * d2) + 10.0f;

        const size_t innq = (size_t)(d * HH + hq) * WW + wq;
        out[(size_t)(b * 3 + 0) * plsz + innq] = (float)d  + d2;
        out[(size_t)(b * 3 + 1) * plsz + innq] = (float)hq + d1;
        out[(size_t)(b * 3 + 2) * plsz + innq] = (float)wq + d0;
        out[(size_t)BB * 3 * plsz + (size_t)b * plsz + innq] = ry;
    }
}

extern "C" void kernel_launch(void* const* d_in, const int* in_sizes, int n_in,
                              void* d_out, int out_size) {
    const float* x = (const float*)d_in[0];
    float* out = (float*)d_out;
    const int total_threads = BB * DD * HH * (WW / 4);   // 1,310,720
    const int block = 256;
    const int grid = total_threads / block;              // 5,120
    quadinterp3d_kernel<<<grid, block>>>(x, out);
}

// round 12
// speedup vs baseline: 1.0425x; 1.0425x over previous
#include <cuda_runtime.h>
#include <cuda_bf16.h>

#define BB 2
#define DD 10
#define HH 512
#define WW 512
#define HW (HH * WW)

__device__ __forceinline__ float4 fmax4(float4 a, float4 b) {
    return make_float4(fmaxf(a.x, b.x), fmaxf(a.y, b.y), fmaxf(a.z, b.z), fmaxf(a.w, b.w));
}

// component jj of quad
__device__ __forceinline__ float selB(float4 v, int jj) {
    float r = v.x;
    r = (jj == 1) ? v.y : r;
    r = (jj == 2) ? v.z : r;
    r = (jj == 3) ? v.w : r;
    return r;
}
// value at wq-1: component jj-1 for jj>=1, else edge scalar e
__device__ __forceinline__ float selA(float4 v, float e, int jj) {
    float r = e;
    r = (jj == 1) ? v.x : r;
    r = (jj == 2) ? v.y : r;
    r = (jj == 3) ? v.z : r;
    return r;
}
// value at wq+1: component jj+1 for jj<=2, else edge scalar e
__device__ __forceinline__ float selC(float4 v, float e, int jj) {
    float r = v.y;
    r = (jj == 1) ? v.z : r;
    r = (jj == 2) ? v.w : r;
    r = (jj == 3) ? e   : r;
    return r;
}

__global__ __launch_bounds__(256, 4)   // 64 regs, 4 CTAs/SM
void quadinterp3d_kernel(const float* __restrict__ x, float* __restrict__ out) {
    // Block = 2 complete W-rows (tid 0-127: h0, tid 128-255: h0+1); same (b,d) per block.
    __shared__ float sCmX[256], sCmW[256], sV4X[256], sV4W[256];
    __shared__ unsigned short q[512];    // (tid<<2 | j) codes of detected maxima
    __shared__ int qcnt;
    __shared__ float4 sRes[1024];        // Newton results indexed by code (16 KB)

    const int tid  = threadIdx.x;
    const int gid  = blockIdx.x * 256 + tid;
    const int lane = tid & 31;
    const int w4 = gid & 127;
    const int h  = (gid >> 7) & 511;
    const int t  = gid >> 16;            // 0..19 (B*D)
    const int d  = t % DD;
    const int b  = t / DD;
    const int w0 = w4 << 2;

    if (tid == 0) qcnt = 0;

    const int off4 = (d * HH + h) * WW;
    const float* __restrict__ base = x + (size_t)b * DD * HW;
    const float* __restrict__ pc = base + off4 + w0;

    // Clamped row deltas (replicate padding); dzm/dzp uniform per block
    const int dym = (h > 0)      ? WW : 0;
    const int dyp = (h < HH - 1) ? WW : 0;
    const int dzm = (d > 0)      ? HW : 0;
    const int dzp = (d < DD - 1) ? HW : 0;

    // Batched independent loads: one aligned float4 per stencil row (MLP=9)
    float4 v0 = *reinterpret_cast<const float4*>(pc - dzm - dym);
    float4 v1 = *reinterpret_cast<const float4*>(pc - dzm);
    float4 v2 = *reinterpret_cast<const float4*>(pc - dzm + dyp);
    float4 v3 = *reinterpret_cast<const float4*>(pc - dym);
    float4 v4 = *reinterpret_cast<const float4*>(pc);
    float4 v5 = *reinterpret_cast<const float4*>(pc + dyp);
    float4 v6 = *reinterpret_cast<const float4*>(pc + dzp - dym);
    float4 v7 = *reinterpret_cast<const float4*>(pc + dzp);
    float4 v8 = *reinterpret_cast<const float4*>(pc + dzp + dyp);

    // Column max of the 8 non-center rows
    float4 cm = fmax4(fmax4(v0, v1), fmax4(v2, v3));
    cm = fmax4(cm, fmax4(fmax4(v5, v6), fmax4(v7, v8)));

    // Block-level edge exchange
    sCmX[tid] = cm.x;  sCmW[tid] = cm.w;
    sV4X[tid] = v4.x;  sV4W[tid] = v4.w;
    __syncthreads();

    const bool atL = (w4 == 0);
    const bool atR = (w4 == 127);
    const float cmL = atL ? cm.x : sCmW[tid - 1];
    const float cmR = atR ? cm.w : sCmX[tid + 1];
    const float u0  = atL ? v4.x : sV4W[tid - 1];
    const float u5  = atR ? v4.w : sV4X[tid + 1];

    // Windowed max over [cmL, cm.x, cm.y, cm.z, cm.w, cmR]
    const float win0 = fmaxf(fmaxf(cmL,  cm.x), cm.y);
    const float win1 = fmaxf(fmaxf(cm.x, cm.y), cm.z);
    const float win2 = fmaxf(fmaxf(cm.y, cm.z), cm.w);
    const float win3 = fmaxf(fmaxf(cm.z, cm.w), cmR);

    // Strict-local-max mask (center row excludes the center element)
    const float nm0 = fmaxf(fmaxf(win0, fmaxf(u0,   v4.y)), 0.0f);
    const float nm1 = fmaxf(fmaxf(win1, fmaxf(v4.x, v4.z)), 0.0f);
    const float nm2 = fmaxf(fmaxf(win2, fmaxf(v4.y, v4.w)), 0.0f);
    const float nm3 = fmaxf(fmaxf(win3, fmaxf(v4.z, u5)),   0.0f);

    const bool m0 = v4.x > nm0;
    const bool m1 = v4.y > nm1;
    const bool m2 = v4.z > nm2;
    const bool m3 = v4.w > nm3;

    // ---- Warp-aggregated queue push: one shared atomic per warp ----
    const unsigned bal0 = __ballot_sync(0xffffffffu, m0);
    const unsigned bal1 = __ballot_sync(0xffffffffu, m1);
    const unsigned bal2 = __ballot_sync(0xffffffffu, m2);
    const unsigned bal3 = __ballot_sync(0xffffffffu, m3);
    const int nWarp = __popc(bal0) + __popc(bal1) + __popc(bal2) + __popc(bal3);
    int basei = 0;
    if (lane == 0 && nWarp) basei = atomicAdd(&qcnt, nWarp);
    basei = __shfl_sync(0xffffffffu, basei, 0);
    {
        const unsigned lm = (1u << lane) - 1u;
        int p = 0;
        if (m0) q[basei + __popc(bal0 & lm)] = (unsigned short)((tid << 2) | 0);
        p += __popc(bal0);
        if (m1) q[basei + p + __popc(bal1 & lm)] = (unsigned short)((tid << 2) | 1);
        p += __popc(bal1);
        if (m2) q[basei + p + __popc(bal2 & lm)] = (unsigned short)((tid << 2) | 2);
        p += __popc(bal2);
        if (m3) q[basei + p + __popc(bal3 & lm)] = (unsigned short)((tid << 2) | 3);
    }
    __syncthreads();

    // ---- Dense queue processing: one thread per maximum.
    //      Gather vectorized: 5 aligned LDG.128 + 4 diagonal scalars
    //      (+5 edge scalars only when jj==0/3). Results handed off via smem. ----
    const int cnt = qcnt;
    for (int i = tid; i < cnt; i += 256) {
        const int code = q[i];
        const int jj   = code & 3;
        const int otid = code >> 2;
        const int wq   = (((otid & 127) << 2) | jj);
        const int hq   = (blockIdx.x * 2 + (otid >> 7)) & 511;
        const int wb   = wq & ~3;                       // aligned quad base

        const float* __restrict__ rowc = base + (d * HH + hq) * WW;
        const int qym = (hq > 0)      ? WW : 0;
        const int qyp = (hq < HH - 1) ? WW : 0;

        // 5 aligned quads (mid rows) — each contains [wq-1, wq, wq+1] when jj is 1 or 2
        const float4 Q4 = *reinterpret_cast<const float4*>(rowc + wb);
        const float4 Q3 = *reinterpret_cast<const float4*>(rowc - qym + wb);
        const float4 Q5 = *reinterpret_cast<const float4*>(rowc + qyp + wb);
        const float4 Q1 = *reinterpret_cast<const float4*>(rowc - dzm + wb);
        const float4 Q7 = *reinterpret_cast<const float4*>(rowc + dzp + wb);

        // 4 diagonal scalars (center column only)
        const float e0 = __ldg(rowc - dzm - qym + wq);
        const float e2 = __ldg(rowc - dzm + qyp + wq);
        const float e6 = __ldg(rowc + dzp - qym + wq);
        const float e8 = __ldg(rowc + dzp + qyp + wq);

        // Edge scalars: one column outside the quad, needed only for jj==0 / jj==3
        const bool eLz = (jj == 0), eRz = (jj == 3);
        float x4 = 0.f, x3 = 0.f, x5 = 0.f, x1 = 0.f, x7 = 0.f;
        if (eLz | eRz) {
            const int we = eLz ? (wq + ((wq > 0) ? -1 : 0))
                               : (wq + ((wq < WW - 1) ? 1 : 0));
            x4 = __ldg(rowc + we);
            x3 = __ldg(rowc - qym + we);
            x5 = __ldg(rowc + qyp + we);
            x1 = __ldg(rowc - dzm + we);
            x7 = __ldg(rowc + dzp + we);
        }

        const float cc = selB(Q4, jj), a4 = selA(Q4, x4, jj), c4 = selC(Q4, x4, jj);
        const float b3 = selB(Q3, jj), a3 = selA(Q3, x3, jj), c3 = selC(Q3, x3, jj);
        const float b5 = selB(Q5, jj), a5 = selA(Q5, x5, jj), c5 = selC(Q5, x5, jj);
        const float b1 = selB(Q1, jj), a1 = selA(Q1, x1, jj), c1 = selC(Q1, x1, jj);
        const float b7 = selB(Q7, jj), a7 = selA(Q7, x7, jj), c7 = selC(Q7, x7, jj);

        // Newton solve (same algebra as the verified kernels; H symmetric)
        const float gx = 0.5f * (c4 - a4);
        const float gy = 0.5f * (b5 - b3);
        const float gs = 0.5f * (b7 - b1);

        const float h00 = a4 + c4 - 2.0f * cc;
        const float h11 = b3 + b5 - 2.0f * cc;
        const float h22 = b1 + b7 - 2.0f * cc;
        const float h01 = 0.25f * (a3 + c5 - a5 - c3);
        const float h12 = 0.25f * (e0 + e8 - e6 - e2);
        const float h02 = 0.25f * (a1 + c7 - a7 - c1);

        const float c00 = h11 * h22 - h12 * h12;
        const float c01 = h01 * h22 - h12 * h02;
        const float c02 = h01 * h12 - h11 * h02;
        const float det = h00 * c00 - h01 * c01 + h02 * c02;

        const float t1 = gy * h22 - h12 * gs;
        const float t2 = gy * h12 - h11 * gs;
        const float t3 = h01 * gs - gy * h02;

        const float inv = 1.0f / det;
        const float sx = (gx * c00 - h01 * t1 + h02 * t2) * inv;
        const float sy = (h00 * t1 - gx * c01 + h02 * t3) * inv;
        const float ss = (h00 * (h11 * gs - h12 * gy) - h01 * t3 + gx * c02) * inv;

        float d0 = -sx, d1 = -sy, d2 = -ss;
        const float far = fmaxf(fmaxf(fabsf(d0), fabsf(d1)), fabsf(d2));
        if (far > 0.7f) { d0 = 0.0f; d1 = 0.0f; d2 = 0.0f; }

        const float ry = cc + 0.5f * (gx * d0 + gy * d1 + gs * d2) + 10.0f;

        sRes[code] = make_float4(d0, d1, d2, ry);
    }
    __syncthreads();

    // ---- Final stores: each owner composes its 4 output float4s ONCE. ----
    const float fd = (float)d, fh = (float)h, fw = (float)w0;
    float4 rd = make_float4(fd, fd, fd, fd);
    float4 rh = make_float4(fh, fh, fh, fh);
    float4 rw = make_float4(fw, fw + 1.0f, fw + 2.0f, fw + 3.0f);
    float4 ry4 = v4;

    if (m0) { const float4 r = sRes[(tid << 2) | 0];
              rw.x += r.x; rh.x += r.y; rd.x += r.z; ry4.x = r.w; }
    if (m1) { const float4 r = sRes[(tid << 2) | 1];
              rw.y += r.x; rh.y += r.y; rd.y += r.z; ry4.y = r.w; }
    if (m2) { const float4 r = sRes[(tid << 2) | 2];
              rw.z += r.x; rh.z += r.y; rd.z += r.z; ry4.z = r.w; }
    if (m3) { const float4 r = sRes[(tid << 2) | 3];
              rw.w += r.x; rh.w += r.y; rd.w += r.z; ry4.w = r.w; }

    const size_t plsz = (size_t)DD * HW;
    const size_t inner = (size_t)off4 + w0;
    *reinterpret_cast<float4*>(out + (size_t)(b * 3 + 0) * plsz + inner) = rd;
    *reinterpret_cast<float4*>(out + (size_t)(b * 3 + 1) * plsz + inner) = rh;
    *reinterpret_cast<float4*>(out + (size_t)(b * 3 + 2) * plsz + inner) = rw;
    *reinterpret_cast<float4*>(out + (size_t)BB * 3 * plsz + (size_t)b * plsz + inner) = ry4;
}

extern "C" void kernel_launch(void* const* d_in, const int* in_sizes, int n_in,
                              void* d_out, int out_size) {
    const float* x = (const float*)d_in[0];
    float* out = (float*)d_out;
    const int total_threads = BB * DD * HH * (WW / 4);   // 1,310,720
    const int block = 256;
    const int grid = total_threads / block;              // 5,120
    quadinterp3d_kernel<<<grid, block>>>(x, out);
}

// round 13
// speedup vs baseline: 1.2526x; 1.2015x over previous
#include <cuda_runtime.h>
#include <cuda_bf16.h>

#define BB 2
#define DD 10
#define HH 512
#define WW 512
#define HW (HH * WW)

__device__ __forceinline__ float4 fmax4(float4 a, float4 b) {
    return make_float4(fmaxf(a.x, b.x), fmaxf(a.y, b.y), fmaxf(a.z, b.z), fmaxf(a.w, b.w));
}

// component jj of quad
__device__ __forceinline__ float selB(float4 v, int jj) {
    float r = v.x;
    r = (jj == 1) ? v.y : r;
    r = (jj == 2) ? v.z : r;
    r = (jj == 3) ? v.w : r;
    return r;
}
// value at wq-1: component jj-1 for jj>=1, else edge scalar e
__device__ __forceinline__ float selA(float4 v, float e, int jj) {
    float r = e;
    r = (jj == 1) ? v.x : r;
    r = (jj == 2) ? v.y : r;
    r = (jj == 3) ? v.z : r;
    return r;
}
// value at wq+1: component jj+1 for jj<=2, else edge scalar e
__device__ __forceinline__ float selC(float4 v, float e, int jj) {
    float r = v.y;
    r = (jj == 1) ? v.z : r;
    r = (jj == 2) ? v.w : r;
    r = (jj == 3) ? e   : r;
    return r;
}

__global__ __launch_bounds__(256, 4)   // 64 regs, 4 CTAs/SM
void quadinterp3d_kernel(const float* __restrict__ x, float* __restrict__ out) {
    // Block = 2 complete W-rows (tid 0-127: h0, tid 128-255: h0+1); same (b,d) per block.
    __shared__ float sCmX[256], sCmW[256], sV4X[256], sV4W[256];
    __shared__ unsigned short q[512];    // (tid<<2 | j) codes of detected maxima
    __shared__ int qcnt;

    const int tid  = threadIdx.x;
    const int gid  = blockIdx.x * 256 + tid;
    const int lane = tid & 31;
    const int w4 = gid & 127;
    const int h  = (gid >> 7) & 511;
    const int t  = gid >> 16;            // 0..19 (B*D)
    const int d  = t % DD;
    const int b  = t / DD;
    const int w0 = w4 << 2;

    if (tid == 0) qcnt = 0;

    const int off4 = (d * HH + h) * WW;
    const float* __restrict__ base = x + (size_t)b * DD * HW;
    const float* __restrict__ pc = base + off4 + w0;

    // Clamped row deltas (replicate padding); dzm/dzp uniform per block
    const int dym = (h > 0)      ? WW : 0;
    const int dyp = (h < HH - 1) ? WW : 0;
    const int dzm = (d > 0)      ? HW : 0;
    const int dzp = (d < DD - 1) ? HW : 0;

    // Batched independent loads: one aligned float4 per stencil row (MLP=9)
    float4 v0 = *reinterpret_cast<const float4*>(pc - dzm - dym);
    float4 v1 = *reinterpret_cast<const float4*>(pc - dzm);
    float4 v2 = *reinterpret_cast<const float4*>(pc - dzm + dyp);
    float4 v3 = *reinterpret_cast<const float4*>(pc - dym);
    float4 v4 = *reinterpret_cast<const float4*>(pc);
    float4 v5 = *reinterpret_cast<const float4*>(pc + dyp);
    float4 v6 = *reinterpret_cast<const float4*>(pc + dzp - dym);
    float4 v7 = *reinterpret_cast<const float4*>(pc + dzp);
    float4 v8 = *reinterpret_cast<const float4*>(pc + dzp + dyp);

    // Column max of the 8 non-center rows
    float4 cm = fmax4(fmax4(v0, v1), fmax4(v2, v3));
    cm = fmax4(cm, fmax4(fmax4(v5, v6), fmax4(v7, v8)));

    // Block-level edge exchange
    sCmX[tid] = cm.x;  sCmW[tid] = cm.w;
    sV4X[tid] = v4.x;  sV4W[tid] = v4.w;
    __syncthreads();

    const bool atL = (w4 == 0);
    const bool atR = (w4 == 127);
    const float cmL = atL ? cm.x : sCmW[tid - 1];
    const float cmR = atR ? cm.w : sCmX[tid + 1];
    const float u0  = atL ? v4.x : sV4W[tid - 1];
    const float u5  = atR ? v4.w : sV4X[tid + 1];

    // Windowed max over [cmL, cm.x, cm.y, cm.z, cm.w, cmR]
    const float win0 = fmaxf(fmaxf(cmL,  cm.x), cm.y);
    const float win1 = fmaxf(fmaxf(cm.x, cm.y), cm.z);
    const float win2 = fmaxf(fmaxf(cm.y, cm.z), cm.w);
    const float win3 = fmaxf(fmaxf(cm.z, cm.w), cmR);

    // Strict-local-max mask (center row excludes the center element)
    const float nm0 = fmaxf(fmaxf(win0, fmaxf(u0,   v4.y)), 0.0f);
    const float nm1 = fmaxf(fmaxf(win1, fmaxf(v4.x, v4.z)), 0.0f);
    const float nm2 = fmaxf(fmaxf(win2, fmaxf(v4.y, v4.w)), 0.0f);
    const float nm3 = fmaxf(fmaxf(win3, fmaxf(v4.z, u5)),   0.0f);

    const bool m0 = v4.x > nm0;
    const bool m1 = v4.y > nm1;
    const bool m2 = v4.z > nm2;
    const bool m3 = v4.w > nm3;

    // ---- Default stores FIRST (coords = grid, y = x). Queue phase (ordered by
    //      the __syncthreads below) overwrites the maxima entries. ----
    const size_t plsz = (size_t)DD * HW;
    const size_t inner = (size_t)off4 + w0;
    const float fd = (float)d, fh = (float)h, fw = (float)w0;
    *reinterpret_cast<float4*>(out + (size_t)(b * 3 + 0) * plsz + inner) =
        make_float4(fd, fd, fd, fd);
    *reinterpret_cast<float4*>(out + (size_t)(b * 3 + 1) * plsz + inner) =
        make_float4(fh, fh, fh, fh);
    *reinterpret_cast<float4*>(out + (size_t)(b * 3 + 2) * plsz + inner) =
        make_float4(fw, fw + 1.0f, fw + 2.0f, fw + 3.0f);
    *reinterpret_cast<float4*>(out + (size_t)BB * 3 * plsz + (size_t)b * plsz + inner) = v4;

    // ---- Warp-aggregated queue push: one shared atomic per warp ----
    const unsigned bal0 = __ballot_sync(0xffffffffu, m0);
    const unsigned bal1 = __ballot_sync(0xffffffffu, m1);
    const unsigned bal2 = __ballot_sync(0xffffffffu, m2);
    const unsigned bal3 = __ballot_sync(0xffffffffu, m3);
    const int nWarp = __popc(bal0) + __popc(bal1) + __popc(bal2) + __popc(bal3);
    int basei = 0;
    if (lane == 0 && nWarp) basei = atomicAdd(&qcnt, nWarp);
    basei = __shfl_sync(0xffffffffu, basei, 0);
    {
        const unsigned lm = (1u << lane) - 1u;
        int p = 0;
        if (m0) q[basei + __popc(bal0 & lm)] = (unsigned short)((tid << 2) | 0);
        p += __popc(bal0);
        if (m1) q[basei + p + __popc(bal1 & lm)] = (unsigned short)((tid << 2) | 1);
        p += __popc(bal1);
        if (m2) q[basei + p + __popc(bal2 & lm)] = (unsigned short)((tid << 2) | 2);
        p += __popc(bal2);
        if (m3) q[basei + p + __popc(bal3 & lm)] = (unsigned short)((tid << 2) | 3);
    }
    __syncthreads();

    // ---- Dense queue processing: one thread per maximum, direct scattered stores.
    //      Gather vectorized: 5 aligned LDG.128 + 4 diagonal scalars
    //      (+5 edge scalars only when jj==0/3). ----
    const int cnt = qcnt;
    for (int i = tid; i < cnt; i += 256) {
        const int code = q[i];
        const int jj   = code & 3;
        const int otid = code >> 2;
        const int wq   = (((otid & 127) << 2) | jj);
        const int hq   = (blockIdx.x * 2 + (otid >> 7)) & 511;
        const int wb   = wq & ~3;                       // aligned quad base

        const float* __restrict__ rowc = base + (d * HH + hq) * WW;
        const int qym = (hq > 0)      ? WW : 0;
        const int qyp = (hq < HH - 1) ? WW : 0;

        // 5 aligned quads (mid rows) — each contains [wq-1, wq, wq+1] when jj is 1 or 2
        const float4 Q4 = *reinterpret_cast<const float4*>(rowc + wb);
        const float4 Q3 = *reinterpret_cast<const float4*>(rowc - qym + wb);
        const float4 Q5 = *reinterpret_cast<const float4*>(rowc + qyp + wb);
        const float4 Q1 = *reinterpret_cast<const float4*>(rowc - dzm + wb);
        const float4 Q7 = *reinterpret_cast<const float4*>(rowc + dzp + wb);

        // 4 diagonal scalars (center column only)
        const float e0 = __ldg(rowc - dzm - qym + wq);
        const float e2 = __ldg(rowc - dzm + qyp + wq);
        const float e6 = __ldg(rowc + dzp - qym + wq);
        const float e8 = __ldg(rowc + dzp + qyp + wq);

        // Edge scalars: one column outside the quad, needed only for jj==0 / jj==3
        const bool eLz = (jj == 0), eRz = (jj == 3);
        float x4 = 0.f, x3 = 0.f, x5 = 0.f, x1 = 0.f, x7 = 0.f;
        if (eLz | eRz) {
            const int we = eLz ? (wq + ((wq > 0) ? -1 : 0))
                               : (wq + ((wq < WW - 1) ? 1 : 0));
            x4 = __ldg(rowc + we);
            x3 = __ldg(rowc - qym + we);
            x5 = __ldg(rowc + qyp + we);
            x1 = __ldg(rowc - dzm + we);
            x7 = __ldg(rowc + dzp + we);
        }

        const float cc = selB(Q4, jj), a4 = selA(Q4, x4, jj), c4 = selC(Q4, x4, jj);
        const float b3 = selB(Q3, jj), a3 = selA(Q3, x3, jj), c3 = selC(Q3, x3, jj);
        const float b5 = selB(Q5, jj), a5 = selA(Q5, x5, jj), c5 = selC(Q5, x5, jj);
        const float b1 = selB(Q1, jj), a1 = selA(Q1, x1, jj), c1 = selC(Q1, x1, jj);
        const float b7 = selB(Q7, jj), a7 = selA(Q7, x7, jj), c7 = selC(Q7, x7, jj);

        // Newton solve (same algebra as the verified kernels; H symmetric)
        const float gx = 0.5f * (c4 - a4);
        const float gy = 0.5f * (b5 - b3);
        const float gs = 0.5f * (b7 - b1);

        const float h00 = a4 + c4 - 2.0f * cc;
        const float h11 = b3 + b5 - 2.0f * cc;
        const float h22 = b1 + b7 - 2.0f * cc;
        const float h01 = 0.25f * (a3 + c5 - a5 - c3);
        const float h12 = 0.25f * (e0 + e8 - e6 - e2);
        const float h02 = 0.25f * (a1 + c7 - a7 - c1);

        const float c00 = h11 * h22 - h12 * h12;
        const float c01 = h01 * h22 - h12 * h02;
        const float c02 = h01 * h12 - h11 * h02;
        const float det = h00 * c00 - h01 * c01 + h02 * c02;

        const float t1 = gy * h22 - h12 * gs;
        const float t2 = gy * h12 - h11 * gs;
        const float t3 = h01 * gs - gy * h02;

        const float inv = 1.0f / det;
        const float sx = (gx * c00 - h01 * t1 + h02 * t2) * inv;
        const float sy = (h00 * t1 - gx * c01 + h02 * t3) * inv;
        const float ss = (h00 * (h11 * gs - h12 * gy) - h01 * t3 + gx * c02) * inv;

        float d0 = -sx, d1 = -sy, d2 = -ss;
        const float far = fmaxf(fmaxf(fabsf(d0), fabsf(d1)), fabsf(d2));
        if (far > 0.7f) { d0 = 0.0f; d1 = 0.0f; d2 = 0.0f; }

        const float ry = cc + 0.5f * (gx * d0 + gy * d1 + gs * d2) + 10.0f;

        const size_t innq = (size_t)(d * HH + hq) * WW + wq;
        out[(size_t)(b * 3 + 0) * plsz + innq] = (float)d  + d2;
        out[(size_t)(b * 3 + 1) * plsz + innq] = (float)hq + d1;
        out[(size_t)(b * 3 + 2) * plsz + innq] = (float)wq + d0;
        out[(size_t)BB * 3 * plsz + (size_t)b * plsz + innq] = ry;
    }
}

extern "C" void kernel_launch(void* const* d_in, const int* in_sizes, int n_in,
                              void* d_out, int out_size) {
    const float* x = (const float*)d_in[0];
    float* out = (float*)d_out;
    const int total_threads = BB * DD * HH * (WW / 4);   // 1,310,720
    const int block = 256;
    const int grid = total_threads / block;              // 5,120
    quadinterp3d_kernel<<<grid, block>>>(x, out);
}